// round 16
// baseline (speedup 1.0000x reference)
#include <cuda_runtime.h>
#include <cuda_bf16.h>

#define NROWS    8192
#define NF       1024
#define NJ       11                  // knot intervals j = 0..10
#define POLY_N   (NJ * NF)           // 11264 float4 entries
#define SMEM_BYTES (POLY_N * 16)     // 176 KB
#define RB       4                   // rows per batch

__device__ float2 g_stats[NROWS];    // {mu, rstd} per row
__device__ float4 g_poly[POLY_N];    // per-(j, f) cubic coeffs {c0,c1,c2,c3}

// ---- Phase 1: row stats (all blocks) + poly table build (blocks 0..43) ----
__global__ __launch_bounds__(256)
void kan_stats(const float* __restrict__ x, const float* __restrict__ sw)
{
    const int tid  = threadIdx.x;
    const int wid  = tid >> 5;
    const int lane = tid & 31;
    const int row  = blockIdx.x * 8 + wid;

    const float4* xr = reinterpret_cast<const float4*>(x + (size_t)row * NF);

    float sum = 0.0f, sq = 0.0f;
    #pragma unroll
    for (int k = 0; k < 8; k++) {
        const float4 t = xr[k * 32 + lane];
        sum += (t.x + t.y) + (t.z + t.w);
        sq   = fmaf(t.x, t.x, fmaf(t.y, t.y, fmaf(t.z, t.z, fmaf(t.w, t.w, sq))));
    }
    #pragma unroll
    for (int off = 16; off; off >>= 1) {
        sum += __shfl_xor_sync(0xffffffffu, sum, off);
        sq  += __shfl_xor_sync(0xffffffffu, sq,  off);
    }
    if (lane == 0) {
        const float mu = sum * (1.0f / NF);
        g_stats[row] = make_float2(mu,
            rsqrtf(sq * (1.0f / NF) - mu * mu + 1e-5f));
    }

    // Poly build: entry e = j*NF + f (truncation baked in: wk=0 outside 0..7)
    const int e = blockIdx.x * 256 + tid;
    if (e < POLY_N) {
        const int j = e >> 10;        // 0..10
        const int f = e & (NF - 1);
        const int i0 = j - 3;
        float w[4];
        #pragma unroll
        for (int k = 0; k < 4; k++) {
            const int idx = i0 + k;
            w[k] = ((unsigned)idx < 8u) ? sw[f * 8 + idx] : 0.0f;
        }
        float4 c;
        c.x = (w[0] + 4.0f * w[1] + w[2]) * (1.0f / 6.0f);
        c.y = (w[2] - w[0]) * 0.5f;
        c.z = (w[0] - 2.0f * w[1] + w[2]) * 0.5f;
        c.w = (w[3] - w[0]) * (1.0f / 6.0f) + (w[1] - w[2]) * 0.5f;
        g_poly[e] = c;
    }
}

// ---- Phase 2: map; 1 feature/thread, 4 rows/batch, double-buffer prefetch ----
__global__ __launch_bounds__(1024)
void kan_map(const float* __restrict__ x,
             const float* __restrict__ lnw,
             const float* __restrict__ lnb,
             const float* __restrict__ bw,
             const float* __restrict__ grid,
             float* __restrict__ out,
             int nblocks)
{
    extern __shared__ float4 s_poly[];   // 11264 entries, 176 KB

    const int tid = threadIdx.x;         // == feature index

    // Stage poly table: j offset = 16 KB = 0 mod 32 banks -> conflict-free
    // LDS.128 under divergent j.
    #pragma unroll
    for (int i = 0; i < NJ; i++)
        s_poly[i * NF + tid] = g_poly[i * NF + tid];

    const float g0    = grid[0];
    const float g11   = grid[11];
    const float inv_h = 11.0f / (g11 - g0);
    const float h     = (g11 - g0) * (1.0f / 11.0f);

    const float A = lnw[tid] * inv_h;          // LN slope in knot units
    const float G = (lnb[tid] - g0) * inv_h;   // LN offset in knot units
    const float W = bw[tid];

    __syncthreads();

    const int step = RB * nblocks;

    // Double-buffered row batches: 8 LDGs in flight during compute
    float  v[2][RB];
    float2 st[2][RB];

    #pragma unroll
    for (int r = 0; r < RB; r++) {
        const int rr = blockIdx.x + r * nblocks;
        if (rr < NROWS) {
            v[0][r]  = x[(size_t)rr * NF + tid];
            st[0][r] = g_stats[rr];
        }
    }

    int p = 0;
    for (int row0 = blockIdx.x; row0 < NROWS; row0 += step, p ^= 1) {
        // Prefetch next batch into other buffer
        const int nrow0 = row0 + step;
        if (nrow0 < NROWS) {
            #pragma unroll
            for (int r = 0; r < RB; r++) {
                const int rr = nrow0 + r * nblocks;
                if (rr < NROWS) {
                    v[p ^ 1][r]  = x[(size_t)rr * NF + tid];
                    st[p ^ 1][r] = g_stats[rr];
                }
            }
        }

        // RB independent compute chains on current buffer
        float res[RB];
        #pragma unroll
        for (int r = 0; r < RB; r++) {
            const float k1 = st[p][r].y * A;           // rstd * A
            const float k2 = fmaf(-st[p][r].x, k1, G); // G - mu*rstd*A
            const float xn = fmaf(v[p][r], k1, k2);    // knot units
            const float n  = fmaf(xn, h, g0);          // normed value

            const float fj = floorf(xn);
            const int   j  = (int)fj;
            const float t  = xn - fj;
            const int   jc = min(max(j, 0), NJ - 1);

            const float4 c = s_poly[jc * NF + tid];    // one LDS.128
            float s = fmaf(fmaf(fmaf(c.w, t, c.z), t, c.y), t, c.x);
            if ((unsigned)j > 10u) s = 0.0f;           // outside knot span

            // silu(n) = m + m*tanh(m), m = n/2  (MUFU tanh)
            const float m = 0.5f * n;
            float th;
            asm("tanh.approx.f32 %0, %1;" : "=f"(th) : "f"(m));
            res[r] = fmaf(W, fmaf(m, th, m), s);
        }

        #pragma unroll
        for (int r = 0; r < RB; r++) {
            const int rr = row0 + r * nblocks;
            if (rr < NROWS)
                out[(size_t)rr * NF + tid] = res[r];
        }
    }
}

extern "C" void kernel_launch(void* const* d_in, const int* in_sizes, int n_in,
                              void* d_out, int out_size)
{
    const float* x    = (const float*)d_in[0];
    const float* lnw  = (const float*)d_in[1];
    const float* lnb  = (const float*)d_in[2];
    const float* sw   = (const float*)d_in[3];
    const float* bw   = (const float*)d_in[4];
    const float* grid = (const float*)d_in[5];
    float* out = (float*)d_out;

    // Host-side, non-stream calls: run during capture, free at replay.
    int dev = 0, nsm = 148;
    cudaGetDevice(&dev);
    cudaDeviceGetAttribute(&nsm, cudaDevAttrMultiProcessorCount, dev);
    cudaFuncSetAttribute(kan_map,
                         cudaFuncAttributeMaxDynamicSharedMemorySize,
                         SMEM_BYTES);

    kan_stats<<<NROWS / 8, 256>>>(x, sw);
    kan_map<<<nsm, 1024, SMEM_BYTES>>>(x, lnw, lnb, bw, grid, out, nsm);
}

// round 17
// speedup vs baseline: 1.4250x; 1.4250x over previous
#include <cuda_runtime.h>
#include <cuda_bf16.h>

#define NROWS    8192
#define NF       1024
#define NJ       11                  // knot intervals j = 0..10
#define POLY_N   (NJ * NF)           // 11264 float4 entries
#define SMEM_BYTES (POLY_N * 16)     // 176 KB
#define RB       4                   // rows per batch

__device__ float2 g_stats[NROWS];    // {mu, rstd} per row
__device__ float4 g_poly[POLY_N];    // per-(j, f) cubic coeffs {c0,c1,c2,c3}

// ---- Phase 1: row stats (all blocks) + poly table build (blocks 0..43) ----
__global__ __launch_bounds__(256)
void kan_stats(const float* __restrict__ x, const float* __restrict__ sw)
{
    const int tid  = threadIdx.x;
    const int wid  = tid >> 5;
    const int lane = tid & 31;
    const int row  = blockIdx.x * 8 + wid;

    const float4* xr = reinterpret_cast<const float4*>(x + (size_t)row * NF);

    float sum = 0.0f, sq = 0.0f;
    #pragma unroll
    for (int k = 0; k < 8; k++) {
        const float4 t = xr[k * 32 + lane];
        sum += (t.x + t.y) + (t.z + t.w);
        sq   = fmaf(t.x, t.x, fmaf(t.y, t.y, fmaf(t.z, t.z, fmaf(t.w, t.w, sq))));
    }
    #pragma unroll
    for (int off = 16; off; off >>= 1) {
        sum += __shfl_xor_sync(0xffffffffu, sum, off);
        sq  += __shfl_xor_sync(0xffffffffu, sq,  off);
    }
    if (lane == 0) {
        const float mu = sum * (1.0f / NF);
        g_stats[row] = make_float2(mu,
            rsqrtf(sq * (1.0f / NF) - mu * mu + 1e-5f));
    }

    // Poly build: entry e = j*NF + f (truncation baked in: wk=0 outside 0..7)
    const int e = blockIdx.x * 256 + tid;
    if (e < POLY_N) {
        const int j = e >> 10;        // 0..10
        const int f = e & (NF - 1);
        const int i0 = j - 3;
        float w[4];
        #pragma unroll
        for (int k = 0; k < 4; k++) {
            const int idx = i0 + k;
            w[k] = ((unsigned)idx < 8u) ? sw[f * 8 + idx] : 0.0f;
        }
        float4 c;
        c.x = (w[0] + 4.0f * w[1] + w[2]) * (1.0f / 6.0f);
        c.y = (w[2] - w[0]) * 0.5f;
        c.z = (w[0] - 2.0f * w[1] + w[2]) * 0.5f;
        c.w = (w[3] - w[0]) * (1.0f / 6.0f) + (w[1] - w[2]) * 0.5f;
        g_poly[e] = c;
    }
}

// Prefetch batch starting at 'base' into named buffer set (literal indices only)
#define PREFETCH(vb, sb, base)                                         \
    {                                                                  \
        _Pragma("unroll")                                              \
        for (int r = 0; r < RB; r++) {                                 \
            const int rr = (base) + r * nblocks;                       \
            if (rr < NROWS) {                                          \
                vb[r] = x[(size_t)rr * NF + tid];                      \
                sb[r] = g_stats[rr];                                   \
            }                                                          \
        }                                                              \
    }

// Compute + store batch from named buffer set
#define COMPUTE(vb, sb, base)                                          \
    {                                                                  \
        float res[RB];                                                 \
        _Pragma("unroll")                                              \
        for (int r = 0; r < RB; r++) {                                 \
            const float k1 = sb[r].y * A;                              \
            const float k2 = fmaf(-sb[r].x, k1, G);                    \
            const float xn = fmaf(vb[r], k1, k2);                      \
            const float n  = fmaf(xn, h, g0);                          \
            const float fj = floorf(xn);                               \
            const int   j  = (int)fj;                                  \
            const float t  = xn - fj;                                  \
            const int   jc = min(max(j, 0), NJ - 1);                   \
            const float4 c = s_poly[jc * NF + tid];                    \
            float s = fmaf(fmaf(fmaf(c.w, t, c.z), t, c.y), t, c.x);   \
            if ((unsigned)j > 10u) s = 0.0f;                           \
            const float m = 0.5f * n;                                  \
            float th;                                                  \
            asm("tanh.approx.f32 %0, %1;" : "=f"(th) : "f"(m));        \
            res[r] = fmaf(W, fmaf(m, th, m), s);                       \
        }                                                              \
        _Pragma("unroll")                                              \
        for (int r = 0; r < RB; r++) {                                 \
            const int rr = (base) + r * nblocks;                       \
            if (rr < NROWS)                                            \
                out[(size_t)rr * NF + tid] = res[r];                   \
        }                                                              \
    }

// ---- Phase 2: map; 1 feature/thread, 4 rows/batch, 2-stage SW pipeline ----
__global__ __launch_bounds__(1024)
void kan_map(const float* __restrict__ x,
             const float* __restrict__ lnw,
             const float* __restrict__ lnb,
             const float* __restrict__ bw,
             const float* __restrict__ grid,
             float* __restrict__ out,
             int nblocks)
{
    extern __shared__ float4 s_poly[];   // 11264 entries, 176 KB

    const int tid = threadIdx.x;         // == feature index

    // Stage poly table: j offset = 16 KB = 0 mod 32 banks -> conflict-free
    // LDS.128 under divergent j.
    #pragma unroll
    for (int i = 0; i < NJ; i++)
        s_poly[i * NF + tid] = g_poly[i * NF + tid];

    const float g0    = grid[0];
    const float g11   = grid[11];
    const float inv_h = 11.0f / (g11 - g0);
    const float h     = (g11 - g0) * (1.0f / 11.0f);

    const float A = lnw[tid] * inv_h;          // LN slope in knot units
    const float G = (lnb[tid] - g0) * inv_h;   // LN offset in knot units
    const float W = bw[tid];

    __syncthreads();

    const int step = RB * nblocks;

    // Two named buffer sets -> registers (no runtime parity index anywhere)
    float  vA[RB], vB[RB];
    float2 stA[RB], stB[RB];

    int row0 = blockIdx.x;
    PREFETCH(vA, stA, row0)

    for (;;) {
        int nxt = row0 + step;
        if (nxt < NROWS) PREFETCH(vB, stB, nxt)
        COMPUTE(vA, stA, row0)
        row0 = nxt;
        if (row0 >= NROWS) break;

        nxt = row0 + step;
        if (nxt < NROWS) PREFETCH(vA, stA, nxt)
        COMPUTE(vB, stB, row0)
        row0 = nxt;
        if (row0 >= NROWS) break;
    }
}

extern "C" void kernel_launch(void* const* d_in, const int* in_sizes, int n_in,
                              void* d_out, int out_size)
{
    const float* x    = (const float*)d_in[0];
    const float* lnw  = (const float*)d_in[1];
    const float* lnb  = (const float*)d_in[2];
    const float* sw   = (const float*)d_in[3];
    const float* bw   = (const float*)d_in[4];
    const float* grid = (const float*)d_in[5];
    float* out = (float*)d_out;

    // Host-side, non-stream calls: run during capture, free at replay.
    int dev = 0, nsm = 148;
    cudaGetDevice(&dev);
    cudaDeviceGetAttribute(&nsm, cudaDevAttrMultiProcessorCount, dev);
    cudaFuncSetAttribute(kan_map,
                         cudaFuncAttributeMaxDynamicSharedMemorySize,
                         SMEM_BYTES);

    kan_stats<<<NROWS / 8, 256>>>(x, sw);
    kan_map<<<nsm, 1024, SMEM_BYTES>>>(x, lnw, lnb, bw, grid, out, nsm);
}